// round 1
// baseline (speedup 1.0000x reference)
#include <cuda_runtime.h>
#include <math.h>

// Problem constants
#define T_ALL 16
#define B_    32
#define C_    256
#define HW    256
#define KLAG  4
#define TQ    12                 // T_ALL - KLAG
#define CHW   (C_ * HW)          // 65536
#define BCHW  (B_ * CHW)         // 2097152
#define NPAIR (TQ * B_)          // 384
#define NTILE 4                  // 2x2 tiles of 128x128 over the 256x256 output

// Output layout (float32): spk_rec copy, loss, log_score_pos(12*32), log_score_neg(12)
#define SPK_N    (T_ALL * BCHW)          // 33554432
#define OUT_LOSS (SPK_N)
#define OUT_LSP  (SPK_N + 1)
#define OUT_LSN  (SPK_N + 1 + NPAIR)

// Scratch (static device allocations are allowed)
__device__ float g_ctx[(size_t)TQ * BCHW];      // context[t][b][c][hw], t<12 (~100.7 MB)
__device__ float g_ppos[NPAIR * NTILE];
__device__ float g_pneg[NPAIR * NTILE];
__device__ int   g_inv[B_];

// ---------------------------------------------------------------------------
// 1) Leaky-integrate-and-fire scan. One thread per (b,c,h,w) element.
// ---------------------------------------------------------------------------
__global__ void scan_kernel(const float* __restrict__ spk) {
    int i = blockIdx.x * blockDim.x + threadIdx.x;
    if (i >= BCHW) return;
    float mem = 0.0f;
#pragma unroll
    for (int t = 0; t < T_ALL; t++) {
        float inp   = spk[(size_t)t * BCHW + i];
        float reset = (mem > 1.0f) ? 1.0f : 0.0f;
        mem = 0.5f * mem + inp - reset;
        if (t < TQ) {
            g_ctx[(size_t)t * BCHW + i] = (mem > 1.0f) ? 1.0f : 0.0f;
        }
    }
}

// ---------------------------------------------------------------------------
// 2) Inverse permutation of rand_idx
// ---------------------------------------------------------------------------
__global__ void inv_kernel(const int* __restrict__ ridx) {
    int b = threadIdx.x;
    if (b < B_) g_inv[ridx[b]] = b;
}

// ---------------------------------------------------------------------------
// 3) Fused GEMM + bilinear reduction.
//    Per pair (tq, b'): X = W(256x256) @ S(256x256), S = spk[tq+4, b'] (c x p).
//    Accumulate  pos += ctx[tq,b'] .* X   and   neg += ctx[tq, inv[b']] .* X
//    entirely in registers; one partial per 128x128 tile goes to a fixed slot.
//    Classic SGEMM tiling: BM=BN=128, BK=16, 256 threads, 8x8 microtile.
// ---------------------------------------------------------------------------
#define BM 128
#define BN 128
#define BK 16

__global__ __launch_bounds__(256, 2)
void gemm_fused(const float* __restrict__ spk, const float* __restrict__ Wg) {
    const int pair = blockIdx.y;          // 0..383
    const int tq   = pair >> 5;
    const int bp   = pair & 31;           // b'
    const int tile = blockIdx.x;          // 0..3
    const int mblk = tile >> 1;           // o-tile
    const int nblk = tile & 1;            // p-tile

    const float* S    = spk + (size_t)(tq + KLAG) * BCHW + (size_t)bp * CHW; // [c][p]
    const int    bneg = g_inv[bp];

    __shared__ float As[BK][BM];   // As[k][m]
    __shared__ float Bs[BK][BN];   // Bs[k][n]

    const int tid = threadIdx.x;
    const int tx  = tid & 15;      // n-dim thread coord
    const int ty  = tid >> 4;      // m-dim thread coord

    float acc[8][8];
#pragma unroll
    for (int i = 0; i < 8; i++)
#pragma unroll
        for (int j = 0; j < 8; j++) acc[i][j] = 0.0f;

    for (int k0 = 0; k0 < C_; k0 += BK) {
        // Load A tile: rows o in [mblk*128, +128), cols c in [k0, k0+16)
#pragma unroll
        for (int v = 0; v < 2; v++) {
            int lin = v * 256 + tid;          // 0..511 float4 slots
            int row = lin >> 2;               // 0..127
            int c4  = lin & 3;                // float4 index along k
            float4 w4 = *(const float4*)&Wg[(size_t)(mblk * BM + row) * C_ + k0 + c4 * 4];
            As[c4 * 4 + 0][row] = w4.x;
            As[c4 * 4 + 1][row] = w4.y;
            As[c4 * 4 + 2][row] = w4.z;
            As[c4 * 4 + 3][row] = w4.w;
        }
        // Load B tile: rows c in [k0, k0+16), cols p in [nblk*128, +128)
#pragma unroll
        for (int v = 0; v < 2; v++) {
            int lin = v * 256 + tid;          // 0..511 float4 slots
            int r   = lin >> 5;               // 0..15
            int p4  = lin & 31;               // 0..31
            float4 s4 = *(const float4*)&S[(size_t)(k0 + r) * HW + nblk * BN + p4 * 4];
            *(float4*)&Bs[r][p4 * 4] = s4;
        }
        __syncthreads();

#pragma unroll
        for (int kk = 0; kk < BK; kk++) {
            float a[8], b[8];
#pragma unroll
            for (int i = 0; i < 8; i++) a[i] = As[kk][ty * 8 + i];
#pragma unroll
            for (int j = 0; j < 8; j++) b[j] = Bs[kk][tx * 8 + j];
#pragma unroll
            for (int i = 0; i < 8; i++)
#pragma unroll
                for (int j = 0; j < 8; j++) acc[i][j] += a[i] * b[j];
        }
        __syncthreads();
    }

    // Epilogue: dot with context tiles (pos and neg), reduce over block.
    const float* ctxP = g_ctx + (size_t)tq * BCHW + (size_t)bp   * CHW;
    const float* ctxN = g_ctx + (size_t)tq * BCHW + (size_t)bneg * CHW;

    float pp = 0.0f, nn = 0.0f;
#pragma unroll
    for (int i = 0; i < 8; i++) {
        int o = mblk * BM + ty * 8 + i;
#pragma unroll
        for (int j = 0; j < 8; j++) {
            int p  = nblk * BN + tx * 8 + j;
            float cp = __ldg(&ctxP[(size_t)o * HW + p]);
            float cn = __ldg(&ctxN[(size_t)o * HW + p]);
            pp += acc[i][j] * cp;
            nn += acc[i][j] * cn;
        }
    }

#pragma unroll
    for (int off = 16; off > 0; off >>= 1) {
        pp += __shfl_down_sync(0xFFFFFFFFu, pp, off);
        nn += __shfl_down_sync(0xFFFFFFFFu, nn, off);
    }
    __shared__ float rp[8], rn[8];
    int warp = tid >> 5, lane = tid & 31;
    if (lane == 0) { rp[warp] = pp; rn[warp] = nn; }
    __syncthreads();
    if (tid == 0) {
        float sp = 0.0f, sn = 0.0f;
#pragma unroll
        for (int w = 0; w < 8; w++) { sp += rp[w]; sn += rn[w]; }
        g_ppos[pair * NTILE + tile]              = sp;
        g_pneg[(tq * B_ + bneg) * NTILE + tile]  = sn;
    }
}

// ---------------------------------------------------------------------------
// 4) Finalize: scores -> logs -> loss. One block, 384 threads.
// ---------------------------------------------------------------------------
__global__ void finalize_kernel(float* __restrict__ out) {
    __shared__ float s_neg[TQ][B_];
    __shared__ float s_lsp[NPAIR];
    __shared__ float s_lsn[TQ];
    int tid = threadIdx.x;                 // 0..383
    int tq  = tid >> 5, b = tid & 31;

    float sp = 0.0f, sn = 0.0f;
#pragma unroll
    for (int t = 0; t < NTILE; t++) {
        sp += g_ppos[tid * NTILE + t];
        sn += g_pneg[tid * NTILE + t];
    }
    float score_pos = expf(sp * (1.0f / (float)CHW)) + 1e-4f;
    float score_neg = expf(sn * (1.0f / (float)CHW)) + 1e-4f;
    float lsp = logf(score_pos);
    s_neg[tq][b] = score_neg;
    s_lsp[tid]   = lsp;
    out[OUT_LSP + tid] = lsp;
    __syncthreads();
    if (b == 0) {
        float s = 0.0f;
#pragma unroll
        for (int bb = 0; bb < B_; bb++) s += s_neg[tq][bb];
        float lsn = logf(s);
        s_lsn[tq] = lsn;
        out[OUT_LSN + tq] = lsn;
    }
    __syncthreads();
    if (tid == 0) {
        float a = 0.0f;
        for (int i = 0; i < NPAIR; i++) a += (-s_lsp[i] + s_lsn[i >> 5]);
        out[OUT_LOSS] = a * (1.0f / (float)NPAIR);
    }
}

// ---------------------------------------------------------------------------
// Launch. Inputs (metadata order): spk_rec f32, mem_rec f32 (unused),
// weight f32 (256x256), rand_idx i32 (32). Output f32, 33554829 elems.
// ---------------------------------------------------------------------------
extern "C" void kernel_launch(void* const* d_in, const int* in_sizes, int n_in,
                              void* d_out, int out_size) {
    const float* spk  = (const float*)d_in[0];
    const float* Wg   = (const float*)d_in[2];
    const int*   ridx = (const int*)d_in[3];
    float* out = (float*)d_out;

    // 1) spk_rec passthrough
    cudaMemcpyAsync(out, spk, (size_t)SPK_N * sizeof(float),
                    cudaMemcpyDeviceToDevice);

    // 2) context scan
    scan_kernel<<<(BCHW + 255) / 256, 256>>>(spk);

    // 3) inverse permutation
    inv_kernel<<<1, 32>>>(ridx);

    // 4) fused GEMM + bilinear reduction
    dim3 grid(NTILE, NPAIR);
    gemm_fused<<<grid, 256>>>(spk, Wg);

    // 5) finalize scalars
    finalize_kernel<<<1, NPAIR>>>(out);
}

// round 4
// speedup vs baseline: 2.7420x; 2.7420x over previous
#include <cuda_runtime.h>
#include <math.h>

// Problem constants
#define T_ALL 16
#define B_    32
#define C_    256
#define HW    256
#define KLAG  4
#define TQ    12                 // T_ALL - KLAG
#define CHW   (C_ * HW)          // 65536
#define BCHW  (B_ * CHW)         // 2097152
#define NPAIR (TQ * B_)          // 384

// Output layout (float32): spk_rec copy, loss, log_score_pos(12*32), log_score_neg(12)
#define SPK_N    (T_ALL * BCHW)          // 33554432
#define OUT_LOSS (SPK_N)
#define OUT_LSP  (SPK_N + 1)
#define OUT_LSN  (SPK_N + 1 + NPAIR)

// Bit-plane scratch: [t][b][c][hw/32] packed along hw (bit k of word = hw base+k)
#define NWORDS (TQ * BCHW / 32)          // 786432 words (3 MB each)
__device__ unsigned g_ctxb[NWORDS];      // context bits, t = 0..11
__device__ unsigned g_spkb[NWORDS];      // spk bits,     t = 4..15 (stored t-4)
__device__ float    g_ppos[NPAIR];
__device__ float    g_pneg[NPAIR];

// ---------------------------------------------------------------------------
// 1) Fused: output copy + LIF scan + bit-packing of ctx and spk.
//    One thread per (b,c,h,w). All mem values are dyadic rationals -> every
//    fp op is exact -> threshold bits match the reference exactly.
// ---------------------------------------------------------------------------
__global__ __launch_bounds__(256)
void scan_kernel(const float* __restrict__ spk, float* __restrict__ out) {
    const int i    = blockIdx.x * blockDim.x + threadIdx.x;   // 0..BCHW-1
    const int lane = threadIdx.x & 31;
    float mem = 0.0f;
#pragma unroll
    for (int t = 0; t < T_ALL; t++) {
        float inp = spk[t * BCHW + i];
        out[t * BCHW + i] = inp;
        float reset = (mem > 1.0f) ? 1.0f : 0.0f;
        mem = 0.5f * mem + inp - reset;
        if (t >= KLAG) {
            unsigned bal = __ballot_sync(0xFFFFFFFFu, inp > 0.5f);
            if (lane == 0) g_spkb[((t - KLAG) * BCHW + i) >> 5] = bal;
        }
        if (t < TQ) {
            unsigned bal = __ballot_sync(0xFFFFFFFFu, mem > 1.0f);
            if (lane == 0) g_ctxb[(t * BCHW + i) >> 5] = bal;
        }
    }
}

// ---------------------------------------------------------------------------
// 2) Binary "GEMM": score[pair] = (1/CHW) * sum_{o,c} W[o,c] *
//                   popc( ctx_bits[pair,o,:] & spk_bits[pair(,neg),c,:] )
//    One block per (tq,b) pair; thread = c column. S rows in registers,
//    ctx rows broadcast from smem, W reads coalesced (L2-resident).
// ---------------------------------------------------------------------------
__global__ __launch_bounds__(256)
void popc_kernel(const float* __restrict__ Wg, const int* __restrict__ ridx) {
    const int pair = blockIdx.x;          // 0..383
    const int tq   = pair >> 5;
    const int b    = pair & 31;
    const int bn   = ridx[b];             // x_neg source batch

    __shared__ unsigned ctxs[C_][8];      // 8 KB
    const int c = threadIdx.x;            // 0..255

    // Load ctx bit-rows for this (tq,b) into smem (2048 words, coalesced)
    {
        const uint4* src = (const uint4*)(g_ctxb + (size_t)(tq * B_ + b) * C_ * 8);
        ((uint4*)&ctxs[c][0])[0] = src[c * 2 + 0];
        ((uint4*)&ctxs[c][0])[1] = src[c * 2 + 1];
    }

    // Load S bit-rows (pos and neg) for column c into registers
    unsigned sP[8], sN[8];
    {
        const uint4* p = (const uint4*)(g_spkb + ((size_t)(tq * B_ + b)  * C_ + c) * 8);
        const uint4* n = (const uint4*)(g_spkb + ((size_t)(tq * B_ + bn) * C_ + c) * 8);
        uint4 v;
        v = p[0]; sP[0]=v.x; sP[1]=v.y; sP[2]=v.z; sP[3]=v.w;
        v = p[1]; sP[4]=v.x; sP[5]=v.y; sP[6]=v.z; sP[7]=v.w;
        v = n[0]; sN[0]=v.x; sN[1]=v.y; sN[2]=v.z; sN[3]=v.w;
        v = n[1]; sN[4]=v.x; sN[5]=v.y; sN[6]=v.z; sN[7]=v.w;
    }
    __syncthreads();

    float accp = 0.0f, accn = 0.0f;
#pragma unroll 4
    for (int o = 0; o < C_; o++) {
        uint4 c0 = ((const uint4*)&ctxs[o][0])[0];   // broadcast, conflict-free
        uint4 c1 = ((const uint4*)&ctxs[o][0])[1];
        int mp = __popc(c0.x & sP[0]) + __popc(c0.y & sP[1])
               + __popc(c0.z & sP[2]) + __popc(c0.w & sP[3])
               + __popc(c1.x & sP[4]) + __popc(c1.y & sP[5])
               + __popc(c1.z & sP[6]) + __popc(c1.w & sP[7]);
        int mn = __popc(c0.x & sN[0]) + __popc(c0.y & sN[1])
               + __popc(c0.z & sN[2]) + __popc(c0.w & sN[3])
               + __popc(c1.x & sN[4]) + __popc(c1.y & sN[5])
               + __popc(c1.z & sN[6]) + __popc(c1.w & sN[7]);
        float w = __ldg(&Wg[o * C_ + c]);            // coalesced across warp
        accp += w * (float)mp;
        accn += w * (float)mn;
    }

    // Block reduction
#pragma unroll
    for (int off = 16; off > 0; off >>= 1) {
        accp += __shfl_down_sync(0xFFFFFFFFu, accp, off);
        accn += __shfl_down_sync(0xFFFFFFFFu, accn, off);
    }
    __shared__ float rp[8], rn[8];
    const int warp = threadIdx.x >> 5, lane = threadIdx.x & 31;
    if (lane == 0) { rp[warp] = accp; rn[warp] = accn; }
    __syncthreads();
    if (threadIdx.x == 0) {
        float sp = 0.0f, sn = 0.0f;
#pragma unroll
        for (int w = 0; w < 8; w++) { sp += rp[w]; sn += rn[w]; }
        g_ppos[pair] = sp;
        g_pneg[pair] = sn;
    }
}

// ---------------------------------------------------------------------------
// 3) Finalize: scores -> logs -> loss. One block, 384 threads.
// ---------------------------------------------------------------------------
__global__ void finalize_kernel(float* __restrict__ out) {
    __shared__ float s_neg[TQ][B_];
    __shared__ float s_lsp[NPAIR];
    __shared__ float s_lsn[TQ];
    int tid = threadIdx.x;                 // 0..383
    int tq  = tid >> 5, b = tid & 31;

    float sp = g_ppos[tid];
    float sn = g_pneg[tid];
    float score_pos = expf(sp * (1.0f / (float)CHW)) + 1e-4f;
    float score_neg = expf(sn * (1.0f / (float)CHW)) + 1e-4f;
    float lsp = logf(score_pos);
    s_neg[tq][b] = score_neg;
    s_lsp[tid]   = lsp;
    out[OUT_LSP + tid] = lsp;
    __syncthreads();
    if (b == 0) {
        float s = 0.0f;
#pragma unroll
        for (int bb = 0; bb < B_; bb++) s += s_neg[tq][bb];
        float lsn = logf(s);
        s_lsn[tq] = lsn;
        out[OUT_LSN + tq] = lsn;
    }
    __syncthreads();
    if (tid == 0) {
        float a = 0.0f;
        for (int i = 0; i < NPAIR; i++) a += (-s_lsp[i] + s_lsn[i >> 5]);
        out[OUT_LOSS] = a * (1.0f / (float)NPAIR);
    }
}

// ---------------------------------------------------------------------------
// Launch. Inputs (metadata order): spk_rec f32, mem_rec f32 (unused),
// weight f32 (256x256), rand_idx i32 (32). Output f32, 33554829 elems.
// ---------------------------------------------------------------------------
extern "C" void kernel_launch(void* const* d_in, const int* in_sizes, int n_in,
                              void* d_out, int out_size) {
    const float* spk  = (const float*)d_in[0];
    const float* Wg   = (const float*)d_in[2];
    const int*   ridx = (const int*)d_in[3];
    float* out = (float*)d_out;

    // 1) copy + scan + bitpack (single pass over spk)
    scan_kernel<<<BCHW / 256, 256>>>(spk, out);

    // 2) binary GEMM via AND+POPC
    popc_kernel<<<NPAIR, 256>>>(Wg, ridx);

    // 3) finalize scalars
    finalize_kernel<<<1, NPAIR>>>(out);
}

// round 6
// speedup vs baseline: 3.5083x; 1.2795x over previous
#include <cuda_runtime.h>
#include <cuda_bf16.h>
#include <math.h>
#include <stdint.h>

// Problem constants
#define T_ALL 16
#define B_    32
#define C_    256
#define HW    256
#define KLAG  4
#define TQ    12
#define CHW   (C_ * HW)          // 65536
#define BCHW  (B_ * CHW)         // 2097152
#define NPAIR (TQ * B_)          // 384

// Output layout (float32)
#define SPK_N    (T_ALL * BCHW)
#define OUT_LOSS (SPK_N)
#define OUT_LSP  (SPK_N + 1)
#define OUT_LSN  (SPK_N + 1 + NPAIR)

// Bit planes: [t][b][c][8 words]; consistent permutation of hw across all users.
#define NWORDS (TQ * BCHW / 32)
__device__ unsigned g_ctxb[NWORDS];
__device__ unsigned g_spkb[NWORDS];
__device__ float    g_ppos[NPAIR * 2];   // [pair][ohalf]
__device__ float    g_pneg[NPAIR * 2];

// ---------------------------------------------------------------------------
// 1) Fused copy + LIF scan + bitpack, float4-vectorized.
// ---------------------------------------------------------------------------
__global__ __launch_bounds__(256)
void scan_kernel(const float4* __restrict__ spk, float4* __restrict__ out) {
    const int i    = blockIdx.x * 256 + threadIdx.x;   // 0 .. BCHW/4-1
    const int lane = threadIdx.x & 31;
    const int row   = i >> 6;                          // (b,c) row
    const int wbase = row * 8 + ((i & 63) >> 5) * 4;

    float m0 = 0.f, m1 = 0.f, m2 = 0.f, m3 = 0.f;
#pragma unroll
    for (int t = 0; t < T_ALL; t++) {
        float4 v = spk[t * (BCHW / 4) + i];
        out[t * (BCHW / 4) + i] = v;
        float r0 = (m0 > 1.f) ? 1.f : 0.f;
        float r1 = (m1 > 1.f) ? 1.f : 0.f;
        float r2 = (m2 > 1.f) ? 1.f : 0.f;
        float r3 = (m3 > 1.f) ? 1.f : 0.f;
        m0 = 0.5f * m0 + v.x - r0;
        m1 = 0.5f * m1 + v.y - r1;
        m2 = 0.5f * m2 + v.z - r2;
        m3 = 0.5f * m3 + v.w - r3;
        if (t >= KLAG) {
            unsigned b0 = __ballot_sync(0xFFFFFFFFu, v.x > 0.5f);
            unsigned b1 = __ballot_sync(0xFFFFFFFFu, v.y > 0.5f);
            unsigned b2 = __ballot_sync(0xFFFFFFFFu, v.z > 0.5f);
            unsigned b3 = __ballot_sync(0xFFFFFFFFu, v.w > 0.5f);
            if (lane == 0) {
                unsigned* p = &g_spkb[(t - KLAG) * (BCHW / 32) + wbase];
                p[0] = b0; p[1] = b1; p[2] = b2; p[3] = b3;
            }
        }
        if (t < TQ) {
            unsigned c0 = __ballot_sync(0xFFFFFFFFu, m0 > 1.f);
            unsigned c1 = __ballot_sync(0xFFFFFFFFu, m1 > 1.f);
            unsigned c2 = __ballot_sync(0xFFFFFFFFu, m2 > 1.f);
            unsigned c3 = __ballot_sync(0xFFFFFFFFu, m3 > 1.f);
            if (lane == 0) {
                unsigned* p = &g_ctxb[t * (BCHW / 32) + wbase];
                p[0] = c0; p[1] = c1; p[2] = c2; p[3] = c3;
            }
        }
    }
}

// ---------------------------------------------------------------------------
// 2) mma.sync bf16 GEMM + masked-add epilogue (register accumulators).
//    CTA = (pair, ohalf): X[o,hw] = W_half(128 x 256) @ S^T, K = c = 256.
// ---------------------------------------------------------------------------
#define RSTRIDE 264                         // bf16 elems per smem row (528 B)
#define OFF_STAGE 0                         // 2048 u32 = 8192 B (spk bit rows)
#define OFF_MASKP 8192                      // 1024 u32
#define OFF_MASKN 12288                     // 1024 u32
#define OFF_RED   16384                     // 16 f32
#define OFF_BNEG  16448
#define OFF_A     16512                     // 128 x 264 bf16 = 67584 B
#define OFF_B     84096                     // 256 x 264 bf16 = 135168 B
#define SMEM_TOTAL (84096 + 135168)

__device__ __forceinline__ uint32_t smem_u32(const void* p) {
    uint32_t a;
    asm("{ .reg .u64 t; cvta.to.shared.u64 t, %1; cvt.u32.u64 %0, t; }" : "=r"(a) : "l"(p));
    return a;
}
__device__ __forceinline__ void ldsm_x4(uint32_t addr, uint32_t& r0, uint32_t& r1,
                                        uint32_t& r2, uint32_t& r3) {
    asm volatile("ldmatrix.sync.aligned.m8n8.x4.shared.b16 {%0,%1,%2,%3}, [%4];"
                 : "=r"(r0), "=r"(r1), "=r"(r2), "=r"(r3) : "r"(addr));
}
__device__ __forceinline__ void mma_bf16(float* c, const uint32_t* a, const uint32_t* b) {
    asm volatile(
        "mma.sync.aligned.m16n8k16.row.col.f32.bf16.bf16.f32 "
        "{%0,%1,%2,%3}, {%4,%5,%6,%7}, {%8,%9}, {%0,%1,%2,%3};"
        : "+f"(c[0]), "+f"(c[1]), "+f"(c[2]), "+f"(c[3])
        : "r"(a[0]), "r"(a[1]), "r"(a[2]), "r"(a[3]), "r"(b[0]), "r"(b[1]));
}

__global__ __launch_bounds__(256, 1)
void mma_kernel(const float* __restrict__ Wg, const int* __restrict__ ridx) {
    extern __shared__ char smem[];
    unsigned* stage = (unsigned*)(smem + OFF_STAGE);
    unsigned* maskP = (unsigned*)(smem + OFF_MASKP);
    unsigned* maskN = (unsigned*)(smem + OFF_MASKN);
    float*    red   = (float*)(smem + OFF_RED);

    const int tid = threadIdx.x, wid = tid >> 5, lane = tid & 31;
    const int pair = blockIdx.x >> 1, ohalf = blockIdx.x & 1;
    const int tq = pair >> 5, bs = pair & 31;
    const int warpM = wid >> 2, warpN = wid & 3;   // 2 x 4 warp grid

    // inverse permutation: bneg s.t. ridx[bneg] == bs
    if (tid < 32 && ridx[tid] == bs) *(int*)(smem + OFF_BNEG) = tid;

    // Stage spk bit rows (2048 words) + pos ctx mask (this o-half, 1024 words)
    {
        const uint4* src = (const uint4*)(g_spkb + (size_t)(tq * B_ + bs) * 2048);
        ((uint4*)stage)[tid]       = src[tid];
        ((uint4*)stage)[tid + 256] = src[tid + 256];
        const uint4* mp = (const uint4*)(g_ctxb + ((size_t)(tq * B_ + bs) * C_ + ohalf * 128) * 8);
        ((uint4*)maskP)[tid] = mp[tid];
    }
    __syncthreads();
    const int bneg = *(const int*)(smem + OFF_BNEG);
    {
        const uint4* mn = (const uint4*)(g_ctxb + ((size_t)(tq * B_ + bneg) * C_ + ohalf * 128) * 8);
        ((uint4*)maskN)[tid] = mn[tid];
    }

    // Expand A = bf16(W[ohalf*128 ..][:]) into [o][c] rows (RSTRIDE pad)
    {
        const float4* W4 = (const float4*)(Wg + (size_t)ohalf * 128 * C_);
#pragma unroll
        for (int v = 0; v < 32; v++) {
            int lin = v * 256 + tid;                 // 8192 float4
            int o = lin >> 6, c4 = lin & 63;
            float4 w4 = W4[lin];
            __nv_bfloat162 lo = __floats2bfloat162_rn(w4.x, w4.y);
            __nv_bfloat162 hi = __floats2bfloat162_rn(w4.z, w4.w);
            *(uint2*)(smem + OFF_A + o * (RSTRIDE * 2) + c4 * 8) =
                make_uint2(*(uint32_t*)&lo, *(uint32_t*)&hi);
        }
    }
    // Expand B = S^T: row p (packed-hw) = tid, cols c. Bits via smem broadcast.
    {
        const int w = tid >> 5, bit = tid & 31;
        char* browp = smem + OFF_B + tid * (RSTRIDE * 2);
#pragma unroll
        for (int c8 = 0; c8 < 32; c8++) {
            uint32_t h[4];
#pragma unroll
            for (int t2 = 0; t2 < 4; t2++) {
                int c = c8 * 8 + t2 * 2;
                unsigned b0 = (stage[c * 8 + w] >> bit) & 1u;
                unsigned b1 = (stage[(c + 1) * 8 + w] >> bit) & 1u;
                h[t2] = (b0 ? 0x3F80u : 0u) | (b1 ? 0x3F800000u : 0u);
            }
            *(uint4*)(browp + c8 * 16) = make_uint4(h[0], h[1], h[2], h[3]);
        }
    }
    __syncthreads();

    // Mainloop: K = 256 in 16 steps; warp tile 64x64 (4 m-tiles x 8 n-tiles)
    float acc[4][8][4];
#pragma unroll
    for (int mi = 0; mi < 4; mi++)
#pragma unroll
        for (int ni = 0; ni < 8; ni++)
#pragma unroll
            for (int e = 0; e < 4; e++) acc[mi][ni][e] = 0.f;

    const uint32_t aBase = smem_u32(smem + OFF_A);
    const uint32_t bBase = smem_u32(smem + OFF_B);
    const int lrow = lane & 15, lcol = (lane >> 4) * 16;

#pragma unroll
    for (int k0 = 0; k0 < 256; k0 += 16) {
        uint32_t a[4][4], b[8][2];
#pragma unroll
        for (int mi = 0; mi < 4; mi++) {
            uint32_t addr = aBase + (warpM * 64 + mi * 16 + lrow) * (RSTRIDE * 2)
                          + k0 * 2 + lcol;
            ldsm_x4(addr, a[mi][0], a[mi][1], a[mi][2], a[mi][3]);
        }
#pragma unroll
        for (int nb = 0; nb < 4; nb++) {
            uint32_t addr = bBase + (warpN * 64 + nb * 16 + lrow) * (RSTRIDE * 2)
                          + k0 * 2 + lcol;
            uint32_t r0, r1, r2, r3;
            ldsm_x4(addr, r0, r1, r2, r3);
            b[nb * 2 + 0][0] = r0; b[nb * 2 + 0][1] = r2;
            b[nb * 2 + 1][0] = r1; b[nb * 2 + 1][1] = r3;
        }
#pragma unroll
        for (int mi = 0; mi < 4; mi++)
#pragma unroll
            for (int ni = 0; ni < 8; ni++)
                mma_bf16(acc[mi][ni], a[mi], b[ni]);
    }

    // Epilogue: masked adds against ctx bit rows (pos and neg)
    float accp = 0.f, accn = 0.f;
    const int rl = lane >> 2, cl = (lane & 3) << 1;
#pragma unroll
    for (int mi = 0; mi < 4; mi++) {
        int r0 = warpM * 64 + mi * 16 + rl;
        int r1 = r0 + 8;
#pragma unroll
        for (int ni = 0; ni < 8; ni++) {
            int cb = warpN * 64 + ni * 8 + cl;
            int wi = cb >> 5, sh = cb & 31;
            unsigned p0 = maskP[r0 * 8 + wi] >> sh;
            unsigned p1 = maskP[r1 * 8 + wi] >> sh;
            unsigned n0 = maskN[r0 * 8 + wi] >> sh;
            unsigned n1 = maskN[r1 * 8 + wi] >> sh;
            float* c = acc[mi][ni];
            accp += ((p0 & 1u) ? c[0] : 0.f) + ((p0 & 2u) ? c[1] : 0.f)
                  + ((p1 & 1u) ? c[2] : 0.f) + ((p1 & 2u) ? c[3] : 0.f);
            accn += ((n0 & 1u) ? c[0] : 0.f) + ((n0 & 2u) ? c[1] : 0.f)
                  + ((n1 & 1u) ? c[2] : 0.f) + ((n1 & 2u) ? c[3] : 0.f);
        }
    }

#pragma unroll
    for (int off = 16; off > 0; off >>= 1) {
        accp += __shfl_down_sync(0xFFFFFFFFu, accp, off);
        accn += __shfl_down_sync(0xFFFFFFFFu, accn, off);
    }
    if (lane == 0) { red[wid] = accp; red[8 + wid] = accn; }
    __syncthreads();
    if (tid == 0) {
        float sp = 0.f, sn = 0.f;
#pragma unroll
        for (int w = 0; w < 8; w++) { sp += red[w]; sn += red[8 + w]; }
        g_ppos[(tq * B_ + bs)   * 2 + ohalf] = sp;
        g_pneg[(tq * B_ + bneg) * 2 + ohalf] = sn;
    }
}

// ---------------------------------------------------------------------------
// 3) Finalize
// ---------------------------------------------------------------------------
__global__ void finalize_kernel(float* __restrict__ out) {
    __shared__ float s_neg[TQ][B_];
    __shared__ float s_lsp[NPAIR];
    __shared__ float s_lsn[TQ];
    int tid = threadIdx.x;
    int tq = tid >> 5, b = tid & 31;

    float sp = g_ppos[tid * 2] + g_ppos[tid * 2 + 1];
    float sn = g_pneg[tid * 2] + g_pneg[tid * 2 + 1];
    float score_pos = expf(sp * (1.0f / (float)CHW)) + 1e-4f;
    float score_neg = expf(sn * (1.0f / (float)CHW)) + 1e-4f;
    float lsp = logf(score_pos);
    s_neg[tq][b] = score_neg;
    s_lsp[tid]   = lsp;
    out[OUT_LSP + tid] = lsp;
    __syncthreads();
    if (b == 0) {
        float s = 0.0f;
#pragma unroll
        for (int bb = 0; bb < B_; bb++) s += s_neg[tq][bb];
        float lsn = logf(s);
        s_lsn[tq] = lsn;
        out[OUT_LSN + tq] = lsn;
    }
    __syncthreads();
    if (tid == 0) {
        float a = 0.0f;
        for (int i = 0; i < NPAIR; i++) a += (-s_lsp[i] + s_lsn[i >> 5]);
        out[OUT_LOSS] = a * (1.0f / (float)NPAIR);
    }
}

// ---------------------------------------------------------------------------
extern "C" void kernel_launch(void* const* d_in, const int* in_sizes, int n_in,
                              void* d_out, int out_size) {
    const float* spk  = (const float*)d_in[0];
    const float* Wg   = (const float*)d_in[2];
    const int*   ridx = (const int*)d_in[3];
    float* out = (float*)d_out;

    static int configured = 0;
    if (!configured) {
        cudaFuncSetAttribute(mma_kernel, cudaFuncAttributeMaxDynamicSharedMemorySize,
                             SMEM_TOTAL);
        configured = 1;
    }

    scan_kernel<<<BCHW / 4 / 256, 256>>>((const float4*)spk, (float4*)out);
    mma_kernel<<<NPAIR * 2, 256, SMEM_TOTAL>>>(Wg, ridx);
    finalize_kernel<<<1, NPAIR>>>(out);
}

// round 7
// speedup vs baseline: 3.5160x; 1.0022x over previous
#include <cuda_runtime.h>
#include <cuda_bf16.h>
#include <math.h>
#include <stdint.h>

// Problem constants
#define T_ALL 16
#define B_    32
#define C_    256
#define HW    256
#define KLAG  4
#define TQ    12
#define CHW   (C_ * HW)          // 65536
#define BCHW  (B_ * CHW)         // 2097152
#define NPAIR (TQ * B_)          // 384

// Output layout (float32)
#define SPK_N    (T_ALL * BCHW)
#define OUT_LOSS (SPK_N)
#define OUT_LSP  (SPK_N + 1)
#define OUT_LSN  (SPK_N + 1 + NPAIR)

// Bit planes: [t][b][c][8 words]; consistent permutation of hw across all users.
#define NWORDS (TQ * BCHW / 32)
__device__ unsigned g_ctxb[NWORDS];
__device__ unsigned g_spkb[NWORDS];
__device__ float    g_ppos[NPAIR * 2];   // [pair][ohalf]
__device__ float    g_pneg[NPAIR * 2];

// ---------------------------------------------------------------------------
// 1) Fused copy + LIF scan + bitpack, float4-vectorized.
// ---------------------------------------------------------------------------
__global__ __launch_bounds__(256)
void scan_kernel(const float4* __restrict__ spk, float4* __restrict__ out) {
    const int i    = blockIdx.x * 256 + threadIdx.x;   // 0 .. BCHW/4-1
    const int lane = threadIdx.x & 31;
    const int row   = i >> 6;                          // (b,c) row
    const int wbase = row * 8 + ((i & 63) >> 5) * 4;

    float m0 = 0.f, m1 = 0.f, m2 = 0.f, m3 = 0.f;
#pragma unroll
    for (int t = 0; t < T_ALL; t++) {
        float4 v = spk[t * (BCHW / 4) + i];
        out[t * (BCHW / 4) + i] = v;
        float r0 = (m0 > 1.f) ? 1.f : 0.f;
        float r1 = (m1 > 1.f) ? 1.f : 0.f;
        float r2 = (m2 > 1.f) ? 1.f : 0.f;
        float r3 = (m3 > 1.f) ? 1.f : 0.f;
        m0 = 0.5f * m0 + v.x - r0;
        m1 = 0.5f * m1 + v.y - r1;
        m2 = 0.5f * m2 + v.z - r2;
        m3 = 0.5f * m3 + v.w - r3;
        if (t >= KLAG) {
            unsigned b0 = __ballot_sync(0xFFFFFFFFu, v.x > 0.5f);
            unsigned b1 = __ballot_sync(0xFFFFFFFFu, v.y > 0.5f);
            unsigned b2 = __ballot_sync(0xFFFFFFFFu, v.z > 0.5f);
            unsigned b3 = __ballot_sync(0xFFFFFFFFu, v.w > 0.5f);
            if (lane == 0) {
                unsigned* p = &g_spkb[(t - KLAG) * (BCHW / 32) + wbase];
                p[0] = b0; p[1] = b1; p[2] = b2; p[3] = b3;
            }
        }
        if (t < TQ) {
            unsigned c0 = __ballot_sync(0xFFFFFFFFu, m0 > 1.f);
            unsigned c1 = __ballot_sync(0xFFFFFFFFu, m1 > 1.f);
            unsigned c2 = __ballot_sync(0xFFFFFFFFu, m2 > 1.f);
            unsigned c3 = __ballot_sync(0xFFFFFFFFu, m3 > 1.f);
            if (lane == 0) {
                unsigned* p = &g_ctxb[t * (BCHW / 32) + wbase];
                p[0] = c0; p[1] = c1; p[2] = c2; p[3] = c3;
            }
        }
    }
}

// ---------------------------------------------------------------------------
// 2) mma.sync bf16 GEMM + masked-add epilogue (register accumulators).
//    CTA = (pair, ohalf): X[o,hw] = W_half(128 x 256) @ S^T, K = c = 256.
// ---------------------------------------------------------------------------
#define RSTRIDE 264                         // bf16 elems per smem row (528 B)
#define OFF_STAGE 0                         // 2048 u32 = 8192 B (spk bit rows)
#define OFF_MASKP 8192                      // 1024 u32
#define OFF_MASKN 12288                     // 1024 u32
#define OFF_RED   16384                     // 16 f32
#define OFF_BNEG  16448
#define OFF_A     16512                     // 128 x 264 bf16 = 67584 B
#define OFF_B     84096                     // 256 x 264 bf16 = 135168 B
#define SMEM_TOTAL (84096 + 135168)

__device__ __forceinline__ uint32_t smem_u32(const void* p) {
    uint32_t a;
    asm("{ .reg .u64 t; cvta.to.shared.u64 t, %1; cvt.u32.u64 %0, t; }" : "=r"(a) : "l"(p));
    return a;
}
__device__ __forceinline__ void ldsm_x4(uint32_t addr, uint32_t& r0, uint32_t& r1,
                                        uint32_t& r2, uint32_t& r3) {
    asm volatile("ldmatrix.sync.aligned.m8n8.x4.shared.b16 {%0,%1,%2,%3}, [%4];"
                 : "=r"(r0), "=r"(r1), "=r"(r2), "=r"(r3) : "r"(addr));
}
__device__ __forceinline__ void mma_bf16(float* c, const uint32_t* a, const uint32_t* b) {
    asm volatile(
        "mma.sync.aligned.m16n8k16.row.col.f32.bf16.bf16.f32 "
        "{%0,%1,%2,%3}, {%4,%5,%6,%7}, {%8,%9}, {%0,%1,%2,%3};"
        : "+f"(c[0]), "+f"(c[1]), "+f"(c[2]), "+f"(c[3])
        : "r"(a[0]), "r"(a[1]), "r"(a[2]), "r"(a[3]), "r"(b[0]), "r"(b[1]));
}

__global__ __launch_bounds__(256, 1)
void mma_kernel(const float* __restrict__ Wg, const int* __restrict__ ridx) {
    extern __shared__ char smem[];
    unsigned* stage = (unsigned*)(smem + OFF_STAGE);
    unsigned* maskP = (unsigned*)(smem + OFF_MASKP);
    unsigned* maskN = (unsigned*)(smem + OFF_MASKN);
    float*    red   = (float*)(smem + OFF_RED);

    const int tid = threadIdx.x, wid = tid >> 5, lane = tid & 31;
    const int pair = blockIdx.x >> 1, ohalf = blockIdx.x & 1;
    const int tq = pair >> 5, bs = pair & 31;
    const int warpM = wid >> 2, warpN = wid & 3;   // 2 x 4 warp grid

    // inverse permutation: bneg s.t. ridx[bneg] == bs
    if (tid < 32 && ridx[tid] == bs) *(int*)(smem + OFF_BNEG) = tid;

    // Stage spk bit rows (2048 words) + pos ctx mask (this o-half, 1024 words)
    {
        const uint4* src = (const uint4*)(g_spkb + (size_t)(tq * B_ + bs) * 2048);
        ((uint4*)stage)[tid]       = src[tid];
        ((uint4*)stage)[tid + 256] = src[tid + 256];
        const uint4* mp = (const uint4*)(g_ctxb + ((size_t)(tq * B_ + bs) * C_ + ohalf * 128) * 8);
        ((uint4*)maskP)[tid] = mp[tid];
    }
    __syncthreads();
    const int bneg = *(const int*)(smem + OFF_BNEG);
    {
        const uint4* mn = (const uint4*)(g_ctxb + ((size_t)(tq * B_ + bneg) * C_ + ohalf * 128) * 8);
        ((uint4*)maskN)[tid] = mn[tid];
    }

    // Expand A = bf16(W[ohalf*128 ..][:]) into [o][c] rows (RSTRIDE pad)
    {
        const float4* W4 = (const float4*)(Wg + (size_t)ohalf * 128 * C_);
#pragma unroll
        for (int v = 0; v < 32; v++) {
            int lin = v * 256 + tid;                 // 8192 float4
            int o = lin >> 6, c4 = lin & 63;
            float4 w4 = W4[lin];
            __nv_bfloat162 lo = __floats2bfloat162_rn(w4.x, w4.y);
            __nv_bfloat162 hi = __floats2bfloat162_rn(w4.z, w4.w);
            *(uint2*)(smem + OFF_A + o * (RSTRIDE * 2) + c4 * 8) =
                make_uint2(*(uint32_t*)&lo, *(uint32_t*)&hi);
        }
    }
    // Expand B = S^T: row p (packed-hw) = tid, cols c. Bits via smem broadcast.
    {
        const int w = tid >> 5, bit = tid & 31;
        char* browp = smem + OFF_B + tid * (RSTRIDE * 2);
#pragma unroll
        for (int c8 = 0; c8 < 32; c8++) {
            uint32_t h[4];
#pragma unroll
            for (int t2 = 0; t2 < 4; t2++) {
                int c = c8 * 8 + t2 * 2;
                unsigned b0 = (stage[c * 8 + w] >> bit) & 1u;
                unsigned b1 = (stage[(c + 1) * 8 + w] >> bit) & 1u;
                h[t2] = (b0 ? 0x3F80u : 0u) | (b1 ? 0x3F800000u : 0u);
            }
            *(uint4*)(browp + c8 * 16) = make_uint4(h[0], h[1], h[2], h[3]);
        }
    }
    __syncthreads();

    // Mainloop: K = 256 in 16 steps; warp tile 64x64 (4 m-tiles x 8 n-tiles)
    float acc[4][8][4];
#pragma unroll
    for (int mi = 0; mi < 4; mi++)
#pragma unroll
        for (int ni = 0; ni < 8; ni++)
#pragma unroll
            for (int e = 0; e < 4; e++) acc[mi][ni][e] = 0.f;

    const uint32_t aBase = smem_u32(smem + OFF_A);
    const uint32_t bBase = smem_u32(smem + OFF_B);
    const int lrow = lane & 15, lcol = (lane >> 4) * 16;

#pragma unroll
    for (int k0 = 0; k0 < 256; k0 += 16) {
        uint32_t a[4][4], b[8][2];
#pragma unroll
        for (int mi = 0; mi < 4; mi++) {
            uint32_t addr = aBase + (warpM * 64 + mi * 16 + lrow) * (RSTRIDE * 2)
                          + k0 * 2 + lcol;
            ldsm_x4(addr, a[mi][0], a[mi][1], a[mi][2], a[mi][3]);
        }
#pragma unroll
        for (int nb = 0; nb < 4; nb++) {
            uint32_t addr = bBase + (warpN * 64 + nb * 16 + lrow) * (RSTRIDE * 2)
                          + k0 * 2 + lcol;
            uint32_t r0, r1, r2, r3;
            ldsm_x4(addr, r0, r1, r2, r3);
            b[nb * 2 + 0][0] = r0; b[nb * 2 + 0][1] = r2;
            b[nb * 2 + 1][0] = r1; b[nb * 2 + 1][1] = r3;
        }
#pragma unroll
        for (int mi = 0; mi < 4; mi++)
#pragma unroll
            for (int ni = 0; ni < 8; ni++)
                mma_bf16(acc[mi][ni], a[mi], b[ni]);
    }

    // Epilogue: masked adds against ctx bit rows (pos and neg)
    float accp = 0.f, accn = 0.f;
    const int rl = lane >> 2, cl = (lane & 3) << 1;
#pragma unroll
    for (int mi = 0; mi < 4; mi++) {
        int r0 = warpM * 64 + mi * 16 + rl;
        int r1 = r0 + 8;
#pragma unroll
        for (int ni = 0; ni < 8; ni++) {
            int cb = warpN * 64 + ni * 8 + cl;
            int wi = cb >> 5, sh = cb & 31;
            unsigned p0 = maskP[r0 * 8 + wi] >> sh;
            unsigned p1 = maskP[r1 * 8 + wi] >> sh;
            unsigned n0 = maskN[r0 * 8 + wi] >> sh;
            unsigned n1 = maskN[r1 * 8 + wi] >> sh;
            float* c = acc[mi][ni];
            accp += ((p0 & 1u) ? c[0] : 0.f) + ((p0 & 2u) ? c[1] : 0.f)
                  + ((p1 & 1u) ? c[2] : 0.f) + ((p1 & 2u) ? c[3] : 0.f);
            accn += ((n0 & 1u) ? c[0] : 0.f) + ((n0 & 2u) ? c[1] : 0.f)
                  + ((n1 & 1u) ? c[2] : 0.f) + ((n1 & 2u) ? c[3] : 0.f);
        }
    }

#pragma unroll
    for (int off = 16; off > 0; off >>= 1) {
        accp += __shfl_down_sync(0xFFFFFFFFu, accp, off);
        accn += __shfl_down_sync(0xFFFFFFFFu, accn, off);
    }
    if (lane == 0) { red[wid] = accp; red[8 + wid] = accn; }
    __syncthreads();
    if (tid == 0) {
        float sp = 0.f, sn = 0.f;
#pragma unroll
        for (int w = 0; w < 8; w++) { sp += red[w]; sn += red[8 + w]; }
        g_ppos[(tq * B_ + bs)   * 2 + ohalf] = sp;
        g_pneg[(tq * B_ + bneg) * 2 + ohalf] = sn;
    }
}

// ---------------------------------------------------------------------------
// 3) Finalize
// ---------------------------------------------------------------------------
__global__ void finalize_kernel(float* __restrict__ out) {
    __shared__ float s_neg[TQ][B_];
    __shared__ float s_lsp[NPAIR];
    __shared__ float s_lsn[TQ];
    int tid = threadIdx.x;
    int tq = tid >> 5, b = tid & 31;

    float sp = g_ppos[tid * 2] + g_ppos[tid * 2 + 1];
    float sn = g_pneg[tid * 2] + g_pneg[tid * 2 + 1];
    float score_pos = expf(sp * (1.0f / (float)CHW)) + 1e-4f;
    float score_neg = expf(sn * (1.0f / (float)CHW)) + 1e-4f;
    float lsp = logf(score_pos);
    s_neg[tq][b] = score_neg;
    s_lsp[tid]   = lsp;
    out[OUT_LSP + tid] = lsp;
    __syncthreads();
    if (b == 0) {
        float s = 0.0f;
#pragma unroll
        for (int bb = 0; bb < B_; bb++) s += s_neg[tq][bb];
        float lsn = logf(s);
        s_lsn[tq] = lsn;
        out[OUT_LSN + tq] = lsn;
    }
    __syncthreads();
    if (tid == 0) {
        float a = 0.0f;
        for (int i = 0; i < NPAIR; i++) a += (-s_lsp[i] + s_lsn[i >> 5]);
        out[OUT_LOSS] = a * (1.0f / (float)NPAIR);
    }
}

// ---------------------------------------------------------------------------
extern "C" void kernel_launch(void* const* d_in, const int* in_sizes, int n_in,
                              void* d_out, int out_size) {
    const float* spk  = (const float*)d_in[0];
    const float* Wg   = (const float*)d_in[2];
    const int*   ridx = (const int*)d_in[3];
    float* out = (float*)d_out;

    static int configured = 0;
    if (!configured) {
        cudaFuncSetAttribute(mma_kernel, cudaFuncAttributeMaxDynamicSharedMemorySize,
                             SMEM_TOTAL);
        configured = 1;
    }

    scan_kernel<<<BCHW / 4 / 256, 256>>>((const float4*)spk, (float4*)out);
    mma_kernel<<<NPAIR * 2, 256, SMEM_TOTAL>>>(Wg, ridx);
    finalize_kernel<<<1, NPAIR>>>(out);
}